// round 1
// baseline (speedup 1.0000x reference)
#include <cuda_runtime.h>
#include <cstdint>
#include <math.h>

#define NT   1024
#define NPIX (8*4*1024*1024)

// ---- static device scratch (no runtime allocation allowed) ----
__device__ int g_B[NT];       // integer threshold boundaries: M > B[k]  <=>  fp32(M*c) > T[k]
__device__ int g_hist[NT];    // ladder-bin histogram
__device__ int g_Bth;         // chosen boundary (final threshold, integer domain)
__device__ int g_M[NPIX];     // exact 25-tap integer sums (blurred image, scaled by 2^23/w)

// c = w * 2^-23 where w = fp32(1/25)  (exact in double)
__device__ __forceinline__ double wscale() {
  const float W = (float)(1.0 / 25.0);
  return (double)W / 8388608.0;
}

// ---------------------------------------------------------------------------
// Kernel 0: build fp32 threshold ladder (exact iterative t -= 0.0005f), convert
// each threshold to an integer boundary B[k] (exact via fp64), zero histogram.
// ---------------------------------------------------------------------------
__global__ void k_init() {
  __shared__ float Tsh[NT];
  if (threadIdx.x == 0) {
    float t = 0.5f;
    for (int k = 0; k < NT; ++k) { Tsh[k] = t; t = t - 0.0005f; }
  }
  __syncthreads();
  const double c = wscale();
  for (int k = threadIdx.x; k < NT; k += blockDim.x) {
    float T = Tsh[k];
    double dM = (double)T / c;
    long long Mg = (long long)floor(dM);
    if (Mg < -1) Mg = -1;
    if (Mg > 400000000LL) Mg = 400000000LL;
    // boundary: max M with fp32(M*c) <= T   (M*c exact in double: <=51 mantissa bits)
    while ((float)((double)(Mg + 1) * c) <= T) Mg++;
    while (Mg >= 0 && (float)((double)Mg * c) > T) Mg--;
    g_B[k] = (int)Mg;
    g_hist[k] = 0;
  }
}

// ---------------------------------------------------------------------------
// Kernel 1: exact integer 5x5 box blur (running sums) + ladder histogram.
// Block: 256 threads, 4 consecutive columns/thread, 64-row band. Grid: 512.
// ---------------------------------------------------------------------------
__global__ void __launch_bounds__(256) k_blur(const float* __restrict__ x) {
  __shared__ int cs[1024];     // column sums for current row
  __shared__ int hist_s[NT];
  __shared__ int Bsh[NT];
  const int tid = threadIdx.x;
  for (int i = tid; i < NT; i += 256) { hist_s[i] = 0; Bsh[i] = g_B[i]; }

  const int ch = blockIdx.x >> 4;
  const int y0 = (blockIdx.x & 15) << 6;
  const float4* xp = (const float4*)x + ((size_t)ch << 18);
  int4* mp = (int4*)g_M + ((size_t)ch << 18);
  __syncthreads();
  const int B0 = Bsh[0];
  int cnt0 = 0;

  auto loadRow = [&](int y) -> int4 {
    int4 m = make_int4(0, 0, 0, 0);
    if ((unsigned)y < 1024u) {
      float4 v = __ldg(xp + ((size_t)y << 8) + tid);
      m.x = (int)(v.x * 8388608.0f);   // exact: uniform values are multiples of 2^-23
      m.y = (int)(v.y * 8388608.0f);
      m.z = (int)(v.z * 8388608.0f);
      m.w = (int)(v.w * 8388608.0f);
    }
    return m;
  };

  auto bin = [&](int M) {
    if (M > B0) { cnt0++; return; }        // v > 0.5 bucket (~50% of pixels, no atomics)
    int k = (int)((float)(B0 - M) * 9.5367432e-06f);   // ~1/104857.6 steps
    if (k < 1) k = 1;
    if (k > NT - 1) k = NT - 1;
    while (k < NT - 1 && M <= Bsh[k]) k++;
    if (M > Bsh[k]) {
      while (k > 1 && M > Bsh[k - 1]) k--;  // smallest k with M > B[k]
      atomicAdd(&hist_s[k], 1);
    }
  };

  int4 r0 = loadRow(y0 - 2);
  int4 r1 = loadRow(y0 - 1);
  int4 r2 = loadRow(y0);
  int4 r3 = loadRow(y0 + 1);
  int4 S;
  S.x = r0.x + r1.x + r2.x + r3.x;
  S.y = r0.y + r1.y + r2.y + r3.y;
  S.z = r0.z + r1.z + r2.z + r3.z;
  S.w = r0.w + r1.w + r2.w + r3.w;

  for (int yy = 0; yy < 64; ++yy) {
    const int y = y0 + yy;
    int4 nw = loadRow(y + 2);
    S.x += nw.x; S.y += nw.y; S.z += nw.z; S.w += nw.w;   // S = rows y-2..y+2
    ((int4*)cs)[tid] = S;
    __syncthreads();
    const int xb = tid << 2;
    const int l2 = tid ? cs[xb - 2] : 0;
    const int l1 = tid ? cs[xb - 1] : 0;
    const int q1 = (tid < 255) ? cs[xb + 4] : 0;
    const int q2 = (tid < 255) ? cs[xb + 5] : 0;
    int4 M;
    M.x = l2 + l1 + S.x + S.y + S.z;
    M.y = M.x - l2 + S.w;
    M.z = M.y - l1 + q1;
    M.w = M.z - S.x + q2;
    mp[((size_t)y << 8) + tid] = M;
    bin(M.x); bin(M.y); bin(M.z); bin(M.w);
    __syncthreads();
    S.x -= r0.x; S.y -= r0.y; S.z -= r0.z; S.w -= r0.w;
    r0 = r1; r1 = r2; r2 = r3; r3 = nw;
  }

  atomicAdd(&hist_s[0], cnt0);
  __syncthreads();
  for (int i = tid; i < NT; i += 256)
    if (hist_s[i]) atomicAdd(&g_hist[i], hist_s[i]);
}

// ---------------------------------------------------------------------------
// Kernel 2: cumulative histogram + exact replay of the two while-loops.
// ---------------------------------------------------------------------------
__global__ void __launch_bounds__(NT) k_search() {
  __shared__ unsigned s[NT];
  const int t = threadIdx.x;
  s[t] = (unsigned)g_hist[t];
  __syncthreads();
  for (int off = 1; off < NT; off <<= 1) {     // inclusive Hillis-Steele scan
    unsigned v = (t >= off) ? s[t - off] : 0u;
    __syncthreads();
    s[t] += v;
    __syncthreads();
  }
  if (t == 0) {
    const float invN = 1.0f / 33554432.0f;     // N = 2^25 exactly
    int a = 0;
    while (a < NT - 1 && (float)s[a] * invN < 0.84f) a++;   // th -= STEP loop
    while (a > 0 && (float)s[a] * invN > 0.86f) a--;        // th += STEP loop (never fires)
    g_Bth = g_B[a];
  }
}

// ---------------------------------------------------------------------------
// Kernel 3: threshold (integer compare) + bitwise morphological close + expand.
// Block: 256 threads, 1024x64 output tile. Grid: 512.
// ---------------------------------------------------------------------------
__global__ void __launch_bounds__(256) k_morph(float* __restrict__ out) {
  __shared__ unsigned bits[72][33];   // thr rows y0-4 .. y0+67
  __shared__ unsigned hd[72][33];     // horizontal dilate
  __shared__ unsigned dv[68][33];     // full dilate, rows y0-2 .. y0+65
  __shared__ unsigned he[68][33];     // horizontal erode of dilate
  const int tid  = threadIdx.x;
  const int lane = tid & 31;
  const int wid  = tid >> 5;
  const int ch = blockIdx.x >> 4;
  const int y0 = (blockIdx.x & 15) << 6;
  const int Bth = g_Bth;
  const int4* mp = (const int4*)g_M + ((size_t)ch << 18);

  // phase 1: build threshold bitmasks (ballot-free nibble assembly)
  for (int r = wid; r < 72; r += 8) {
    const int gy = y0 - 4 + r;
    const bool in = (unsigned)gy < 1024u;      // uniform per warp
    for (int seg = 0; seg < 8; ++seg) {
      unsigned v = 0;
      if (in) {
        int4 m = mp[((size_t)gy << 8) + (seg << 5) + lane];
        unsigned n = (m.x > Bth ? 1u : 0u) | (m.y > Bth ? 2u : 0u)
                   | (m.z > Bth ? 4u : 0u) | (m.w > Bth ? 8u : 0u);
        v = n << ((lane & 7) << 2);
        v |= __shfl_xor_sync(0xFFFFFFFFu, v, 1);
        v |= __shfl_xor_sync(0xFFFFFFFFu, v, 2);
        v |= __shfl_xor_sync(0xFFFFFFFFu, v, 4);
      }
      if ((lane & 7) == 0) bits[r][(seg << 2) + (lane >> 3)] = v;
    }
  }
  __syncthreads();

  // phase 2: horizontal dilate (0-fill = -inf pad)
  for (int idx = tid; idx < 72 * 32; idx += 256) {
    const int r = idx >> 5, w = idx & 31;
    const unsigned u = bits[r][w];
    const unsigned L = w ? bits[r][w - 1] : 0u;
    const unsigned R = (w < 31) ? bits[r][w + 1] : 0u;
    hd[r][w] = u | __funnelshift_r(u, R, 1) | __funnelshift_r(u, R, 2)
                 | __funnelshift_l(L, u, 1) | __funnelshift_l(L, u, 2);
  }
  __syncthreads();

  // phase 3: vertical dilate
  for (int idx = tid; idx < 68 * 32; idx += 256) {
    const int r = idx >> 5, w = idx & 31;
    dv[r][w] = hd[r][w] | hd[r + 1][w] | hd[r + 2][w] | hd[r + 3][w] | hd[r + 4][w];
  }
  __syncthreads();

  // phase 4: horizontal erode (1-fill = +inf pad)
  for (int idx = tid; idx < 68 * 32; idx += 256) {
    const int r = idx >> 5, w = idx & 31;
    const unsigned u = dv[r][w];
    const unsigned L = w ? dv[r][w - 1] : 0xFFFFFFFFu;
    const unsigned R = (w < 31) ? dv[r][w + 1] : 0xFFFFFFFFu;
    he[r][w] = u & __funnelshift_r(u, R, 1) & __funnelshift_r(u, R, 2)
                 & __funnelshift_l(L, u, 1) & __funnelshift_l(L, u, 2);
  }
  __syncthreads();

  // phase 5: vertical erode with image-bound clipping, expand bits -> f32
  float* op = out + ((size_t)ch << 20);
  for (int idx = tid; idx < 64 * 32; idx += 256) {
    const int yy = idx >> 5, w = idx & 31;
    const int gy = y0 + yy;
    int lo = gy - 2; if (lo < 0) lo = 0;
    int hi = gy + 2; if (hi > 1023) hi = 1023;
    unsigned o = 0xFFFFFFFFu;
    for (int g2 = lo; g2 <= hi; ++g2) o &= he[g2 - (y0 - 2)][w];
    float4* dst = (float4*)(op + ((size_t)gy << 10) + (w << 5));
#pragma unroll
    for (int q = 0; q < 8; ++q) {
      float4 f;
      f.x = ((o >> (4 * q    )) & 1u) ? 1.0f : 0.0f;
      f.y = ((o >> (4 * q + 1)) & 1u) ? 1.0f : 0.0f;
      f.z = ((o >> (4 * q + 2)) & 1u) ? 1.0f : 0.0f;
      f.w = ((o >> (4 * q + 3)) & 1u) ? 1.0f : 0.0f;
      dst[q] = f;
    }
  }
}

// ---------------------------------------------------------------------------
extern "C" void kernel_launch(void* const* d_in, const int* in_sizes, int n_in,
                              void* d_out, int out_size) {
  // identify x by size (the other input is the 25-element blur kernel)
  const float* x = (const float*)d_in[0];
  if (n_in > 1 && in_sizes[0] < in_sizes[1]) x = (const float*)d_in[1];

  k_init  <<<1,   256>>>();
  k_blur  <<<512, 256>>>(x);
  k_search<<<1,   NT >>>();
  k_morph <<<512, 256>>>((float*)d_out);
}

// round 2
// speedup vs baseline: 1.1189x; 1.1189x over previous
#include <cuda_runtime.h>
#include <cstdint>
#include <math.h>

#define NT   1024
#define NPIX (8*4*1024*1024)

// ---- static device scratch ----
__device__ int g_B[NT];            // integer boundaries: M > B[k] <=> fp32(M*c) > T[k]
__device__ int g_coarse[16];       // coarse histogram (64-step windows of k)
__device__ int g_fine[64];         // fine histogram within chosen window
__device__ int g_lo, g_cumbelow, g_a;
__device__ unsigned g_bin[NPIX/4]; // per-pixel saturated bin index, 4x uint8 packed

__device__ __forceinline__ double wscale() {
  const float W = (float)(1.0 / 25.0);
  return (double)W / 8388608.0;
}

// ---------------------------------------------------------------------------
// K0: fp32 threshold ladder -> integer boundaries; zero histograms.
// ---------------------------------------------------------------------------
__global__ void k_init() {
  __shared__ float Tsh[NT];
  if (threadIdx.x == 0) {
    float t = 0.5f;
    for (int k = 0; k < NT; ++k) { Tsh[k] = t; t = t - 0.0005f; }
  }
  __syncthreads();
  const double c = wscale();
  for (int k = threadIdx.x; k < NT; k += blockDim.x) {
    float T = Tsh[k];
    double dM = (double)T / c;
    long long Mg = (long long)floor(dM);
    if (Mg < -1) Mg = -1;
    if (Mg > 400000000LL) Mg = 400000000LL;
    while ((float)((double)(Mg + 1) * c) <= T) Mg++;
    while (Mg >= 0 && (float)((double)Mg * c) > T) Mg--;
    g_B[k] = (int)Mg;
  }
  if (threadIdx.x < 16) g_coarse[threadIdx.x] = 0;
  if (threadIdx.x < 64) g_fine[threadIdx.x] = 0;
}

// ---------------------------------------------------------------------------
// K1: exact integer 5x5 box blur, per-pixel exact ladder index k*,
//     uint8 store (sat 255), register-packed coarse counters. NO smem exchange,
//     NO per-pixel atomics. 8 warps = 8 x 128-col segments; 64-row band.
// ---------------------------------------------------------------------------
__global__ void __launch_bounds__(256, 4) k_blur(const float* __restrict__ x) {
  __shared__ int Bsh[NT];
  __shared__ int csh[16];
  const int tid = threadIdx.x, lane = tid & 31, w = tid >> 5;
  for (int i = tid; i < NT; i += 256) Bsh[i] = g_B[i];
  if (tid < 16) csh[tid] = 0;
  __syncthreads();

  const int ch = blockIdx.x >> 4;
  const int y0 = (blockIdx.x & 15) << 6;
  const float4* xo = (const float4*)x + ((size_t)ch << 18);
  const float*  xs = x + ((size_t)ch << 20);
  unsigned* bp = g_bin + ((size_t)ch << 18);

  const int c0 = (w << 7) + (lane << 2);
  const int hcol = (lane == 0) ? (c0 - 2) : (c0 + 4);
  const bool hval = (lane == 0) ? (w > 0) : ((lane == 31) && (w < 7));
  const int B0 = Bsh[0];
  unsigned long long accL = 0ull, accH = 0ull;

  auto ldOwn = [&](int y) -> int4 {
    int4 m = make_int4(0, 0, 0, 0);
    if ((unsigned)y < 1024u) {
      float4 v = __ldg(xo + ((size_t)y << 8) + tid);
      m.x = (int)(v.x * 8388608.0f);
      m.y = (int)(v.y * 8388608.0f);
      m.z = (int)(v.z * 8388608.0f);
      m.w = (int)(v.w * 8388608.0f);
    }
    return m;
  };
  auto ldHalo = [&](int y) -> int2 {
    int2 m = make_int2(0, 0);
    if (hval && (unsigned)y < 1024u) {
      float2 v = __ldg((const float2*)(xs + ((size_t)y << 10) + hcol));
      m.x = (int)(v.x * 8388608.0f);
      m.y = (int)(v.y * 8388608.0f);
    }
    return m;
  };
  auto kidx = [&](int M) -> int {
    int d = B0 - M;
    if (d < 0) return 0;
    int k = (int)((float)d * 9.5367432e-06f);
    if (k < 1) k = 1;
    if (k > NT - 1) k = NT - 1;
    while (k < NT - 1 && M <= Bsh[k]) k++;
    while (k > 1 && M > Bsh[k - 1]) k--;
    return k;
  };
  auto flush = [&]() {
#pragma unroll
    for (int j = 0; j < 8; ++j) {
      int a = (int)((accL >> (j << 3)) & 0xffull);
      int b = (int)((accH >> (j << 3)) & 0xffull);
      if (a) atomicAdd(&csh[j], a);
      if (b) atomicAdd(&csh[8 + j], b);
    }
    accL = accH = 0ull;
  };

  int4 r0 = ldOwn(y0 - 2), r1 = ldOwn(y0 - 1), r2 = ldOwn(y0), r3 = ldOwn(y0 + 1);
  int2 h0 = ldHalo(y0 - 2), h1 = ldHalo(y0 - 1), h2 = ldHalo(y0), h3 = ldHalo(y0 + 1);
  int4 S;
  S.x = r0.x + r1.x + r2.x + r3.x;
  S.y = r0.y + r1.y + r2.y + r3.y;
  S.z = r0.z + r1.z + r2.z + r3.z;
  S.w = r0.w + r1.w + r2.w + r3.w;
  int2 Sh = make_int2(h0.x + h1.x + h2.x + h3.x, h0.y + h1.y + h2.y + h3.y);

  for (int yy = 0; yy < 64; ++yy) {
    const int y = y0 + yy;
    int4 nw = ldOwn(y + 2);
    int2 nh = ldHalo(y + 2);
    S.x += nw.x; S.y += nw.y; S.z += nw.z; S.w += nw.w;
    Sh.x += nh.x; Sh.y += nh.y;

    int l2 = __shfl_up_sync(0xFFFFFFFFu, S.z, 1);
    int l1 = __shfl_up_sync(0xFFFFFFFFu, S.w, 1);
    int q1 = __shfl_down_sync(0xFFFFFFFFu, S.x, 1);
    int q2 = __shfl_down_sync(0xFFFFFFFFu, S.y, 1);
    if (lane == 0)  { l2 = Sh.x; l1 = Sh.y; }
    if (lane == 31) { q1 = Sh.x; q2 = Sh.y; }

    int Mx = l2 + l1 + S.x + S.y + S.z;
    int My = Mx - l2 + S.w;
    int Mz = My - l1 + q1;
    int Mw = Mz - S.x + q2;

    int k0 = kidx(Mx), k1 = kidx(My), k2 = kidx(Mz), k3 = kidx(Mw);
    unsigned p = (unsigned)(k0 > 255 ? 255 : k0)
               | ((unsigned)(k1 > 255 ? 255 : k1) << 8)
               | ((unsigned)(k2 > 255 ? 255 : k2) << 16)
               | ((unsigned)(k3 > 255 ? 255 : k3) << 24);
    bp[((size_t)y << 8) + tid] = p;

    {
      int kc = k0 >> 6; unsigned long long one = 1ull << ((kc & 7) << 3);
      if (kc < 8) accL += one; else accH += one;
      kc = k1 >> 6; one = 1ull << ((kc & 7) << 3);
      if (kc < 8) accL += one; else accH += one;
      kc = k2 >> 6; one = 1ull << ((kc & 7) << 3);
      if (kc < 8) accL += one; else accH += one;
      kc = k3 >> 6; one = 1ull << ((kc & 7) << 3);
      if (kc < 8) accL += one; else accH += one;
    }

    S.x -= r0.x; S.y -= r0.y; S.z -= r0.z; S.w -= r0.w;
    Sh.x -= h0.x; Sh.y -= h0.y;
    r0 = r1; r1 = r2; r2 = r3; r3 = nw;
    h0 = h1; h1 = h2; h2 = h3; h3 = nh;

    if (yy == 31) flush();   // 8-bit fields hold <=128 counts per flush period
  }
  flush();
  __syncthreads();
  if (tid < 16 && csh[tid]) atomicAdd(&g_coarse[tid], csh[tid]);
}

// ---------------------------------------------------------------------------
// K2a: pick the 64-step window containing the 0.84 crossing (float-compare
//      semantics identical to the reference while-loop).
// ---------------------------------------------------------------------------
__global__ void k2a() {
  const float invN = 1.0f / 33554432.0f;   // N = 2^25
  int cum = 0, jstar = -1, cumb = 0;
  for (int j = 0; j < 16; ++j) {
    int nc = cum + g_coarse[j];
    if ((float)nc * invN >= 0.84f) { jstar = j; cumb = cum; cum = nc; break; }
    cum = nc;
  }
  if (jstar < 0) { jstar = 15; cumb = cum - g_coarse[15]; }
  g_lo = jstar << 6;
  g_cumbelow = cumb;
}

// ---------------------------------------------------------------------------
// K2b: fine histogram, atomics only for pixels inside the 64-bin window.
// ---------------------------------------------------------------------------
__global__ void __launch_bounds__(256) k2b() {
  __shared__ int f[64];
  const int tid = threadIdx.x;
  if (tid < 64) f[tid] = 0;
  __syncthreads();
  const unsigned lo = (unsigned)g_lo;
  const uint4* p = (const uint4*)g_bin;
  const int n = NPIX / 16;
  for (int i = blockIdx.x * 256 + tid; i < n; i += gridDim.x * 256) {
    uint4 v = __ldg(p + i);
#pragma unroll
    for (int q = 0; q < 4; ++q) {
      unsigned word = (q == 0) ? v.x : (q == 1) ? v.y : (q == 2) ? v.z : v.w;
#pragma unroll
      for (int b = 0; b < 4; ++b) {
        unsigned t = ((word >> (b << 3)) & 0xffu) - lo;
        if (t < 64u) atomicAdd(&f[t], 1);
      }
    }
  }
  __syncthreads();
  if (tid < 64 && f[tid]) atomicAdd(&g_fine[tid], f[tid]);
}

// ---------------------------------------------------------------------------
// K2c: replay both while-loops exactly on exact counts -> final bin index a.
// ---------------------------------------------------------------------------
__global__ void k2c() {
  const float invN = 1.0f / 33554432.0f;
  int cum = g_cumbelow;
  const int lo = g_lo;
  int i = 0;
  for (; i < 64; ++i) {
    cum += g_fine[i];
    if ((float)cum * invN >= 0.84f) break;
  }
  if (i >= 64) i = 63;
  int a = lo + i;
  if ((float)cum * invN > 0.86f) a -= 1;   // second loop: at most one step back
  g_a = a;
}

// ---------------------------------------------------------------------------
// K3: threshold (v <= a on uint8 bins) + bitwise morphological close + expand.
// 1024x32 tiles, grid 1024, ~20KB smem.
// ---------------------------------------------------------------------------
__global__ void __launch_bounds__(256) k_morph(float* __restrict__ out) {
  __shared__ unsigned bits[40][33];   // thr rows y0-4 .. y0+35
  __shared__ unsigned hd[40][33];     // horizontal dilate
  __shared__ unsigned dv[36][33];     // full dilate, rows y0-2 .. y0+33
  __shared__ unsigned he[36][33];     // horizontal erode of dilate
  const int tid  = threadIdx.x;
  const int lane = tid & 31;
  const int wid  = tid >> 5;
  const int ch = blockIdx.x >> 5;
  const int y0 = (blockIdx.x & 31) << 5;
  const int a = g_a;
  const unsigned* bw = g_bin + ((size_t)ch << 18);

  // phase 1: threshold bitmasks from packed uint8 bins
  for (int r = wid; r < 40; r += 8) {
    const int gy = y0 - 4 + r;
    const bool in = (unsigned)gy < 1024u;
    for (int seg = 0; seg < 8; ++seg) {
      unsigned v = 0;
      if (in) {
        unsigned pk = __ldg(&bw[((size_t)gy << 8) + (seg << 5) + lane]);
        unsigned n = ((int)( pk        & 0xff) <= a ? 1u : 0u)
                   | ((int)((pk >> 8)  & 0xff) <= a ? 2u : 0u)
                   | ((int)((pk >> 16) & 0xff) <= a ? 4u : 0u)
                   | ((int)((pk >> 24) & 0xff) <= a ? 8u : 0u);
        v = n << ((lane & 7) << 2);
        v |= __shfl_xor_sync(0xFFFFFFFFu, v, 1);
        v |= __shfl_xor_sync(0xFFFFFFFFu, v, 2);
        v |= __shfl_xor_sync(0xFFFFFFFFu, v, 4);
      }
      if ((lane & 7) == 0) bits[r][(seg << 2) + (lane >> 3)] = v;
    }
  }
  __syncthreads();

  // phase 2: horizontal dilate (0-fill)
  for (int idx = tid; idx < 40 * 32; idx += 256) {
    const int r = idx >> 5, w = idx & 31;
    const unsigned u = bits[r][w];
    const unsigned L = w ? bits[r][w - 1] : 0u;
    const unsigned R = (w < 31) ? bits[r][w + 1] : 0u;
    hd[r][w] = u | __funnelshift_r(u, R, 1) | __funnelshift_r(u, R, 2)
                 | __funnelshift_l(L, u, 1) | __funnelshift_l(L, u, 2);
  }
  __syncthreads();

  // phase 3: vertical dilate
  for (int idx = tid; idx < 36 * 32; idx += 256) {
    const int r = idx >> 5, w = idx & 31;
    dv[r][w] = hd[r][w] | hd[r + 1][w] | hd[r + 2][w] | hd[r + 3][w] | hd[r + 4][w];
  }
  __syncthreads();

  // phase 4: horizontal erode (1-fill)
  for (int idx = tid; idx < 36 * 32; idx += 256) {
    const int r = idx >> 5, w = idx & 31;
    const unsigned u = dv[r][w];
    const unsigned L = w ? dv[r][w - 1] : 0xFFFFFFFFu;
    const unsigned R = (w < 31) ? dv[r][w + 1] : 0xFFFFFFFFu;
    he[r][w] = u & __funnelshift_r(u, R, 1) & __funnelshift_r(u, R, 2)
                 & __funnelshift_l(L, u, 1) & __funnelshift_l(L, u, 2);
  }
  __syncthreads();

  // phase 5: vertical erode (clipped = +inf pad), expand bits -> f32
  float* op = out + ((size_t)ch << 20);
  for (int idx = tid; idx < 32 * 32; idx += 256) {
    const int yy = idx >> 5, w = idx & 31;
    const int gy = y0 + yy;
    int lo = gy - 2; if (lo < 0) lo = 0;
    int hi = gy + 2; if (hi > 1023) hi = 1023;
    unsigned o = 0xFFFFFFFFu;
    for (int g2 = lo; g2 <= hi; ++g2) o &= he[g2 - (y0 - 2)][w];
    float4* dst = (float4*)(op + ((size_t)gy << 10) + (w << 5));
#pragma unroll
    for (int q = 0; q < 8; ++q) {
      float4 f;
      f.x = ((o >> (4 * q    )) & 1u) ? 1.0f : 0.0f;
      f.y = ((o >> (4 * q + 1)) & 1u) ? 1.0f : 0.0f;
      f.z = ((o >> (4 * q + 2)) & 1u) ? 1.0f : 0.0f;
      f.w = ((o >> (4 * q + 3)) & 1u) ? 1.0f : 0.0f;
      dst[q] = f;
    }
  }
}

// ---------------------------------------------------------------------------
extern "C" void kernel_launch(void* const* d_in, const int* in_sizes, int n_in,
                              void* d_out, int out_size) {
  const float* x = (const float*)d_in[0];
  if (n_in > 1 && in_sizes[0] < in_sizes[1]) x = (const float*)d_in[1];

  k_init <<<1,    256>>>();
  k_blur <<<512,  256>>>(x);
  k2a    <<<1,    1  >>>();
  k2b    <<<1024, 256>>>();
  k2c    <<<1,    1  >>>();
  k_morph<<<1024, 256>>>((float*)d_out);
}

// round 3
// speedup vs baseline: 1.2669x; 1.1323x over previous
#include <cuda_runtime.h>
#include <cstdint>
#include <math.h>

#define NT   1024
#define NPIX (8*4*1024*1024)

// ---- static device scratch ----
__device__ int g_B[NT];            // integer boundaries: M > B[k] <=> fp32(M*c) > T[k]
__device__ int g_coarse[16];       // coarse histogram (64-step windows of k)
__device__ int g_fine[64];         // fine histogram within chosen window
__device__ int g_lo, g_cumbelow, g_a;
__device__ unsigned g_bin[NPIX/4]; // per-pixel exact ladder index, 4x uint8 packed (sat 255)

__device__ __forceinline__ double wscale() {
  const float W = (float)(1.0 / 25.0);
  return (double)W / 8388608.0;
}

// ---------------------------------------------------------------------------
// K0: fp32 threshold ladder -> integer boundaries; zero histograms.
// ---------------------------------------------------------------------------
__global__ void k_init() {
  __shared__ float Tsh[NT];
  if (threadIdx.x == 0) {
    float t = 0.5f;
    for (int k = 0; k < NT; ++k) { Tsh[k] = t; t = t - 0.0005f; }
  }
  __syncthreads();
  const double c = wscale();
  for (int k = threadIdx.x; k < NT; k += blockDim.x) {
    float T = Tsh[k];
    double dM = (double)T / c;
    long long Mg = (long long)floor(dM);
    if (Mg < -1) Mg = -1;
    if (Mg > 400000000LL) Mg = 400000000LL;
    while ((float)((double)(Mg + 1) * c) <= T) Mg++;
    while (Mg >= 0 && (float)((double)Mg * c) > T) Mg--;
    g_B[k] = (int)Mg;
  }
  if (threadIdx.x < 16) g_coarse[threadIdx.x] = 0;
  if (threadIdx.x < 64) g_fine[threadIdx.x] = 0;
}

// ---------------------------------------------------------------------------
// K1: exact integer 5x5 box blur (running sums), exact ladder index k* per px,
//     uint8 store, register-packed coarse counters. No per-pixel atomics.
//     8 warps = 8 x 128-col strips; 32-row band. Grid 1024. NO reg cap.
// ---------------------------------------------------------------------------
__global__ void __launch_bounds__(256) k_blur(const float* __restrict__ x) {
  __shared__ int Bsh[NT];
  __shared__ int csh[16];
  const int tid = threadIdx.x, lane = tid & 31, w = tid >> 5;
  for (int i = tid; i < NT; i += 256) Bsh[i] = g_B[i];
  if (tid < 16) csh[tid] = 0;
  __syncthreads();

  const int ch = blockIdx.x >> 5;
  const int y0 = (blockIdx.x & 31) << 5;
  const float4* xo = (const float4*)x + ((size_t)ch << 18);
  const float*  xs = x + ((size_t)ch << 20);
  unsigned* bp = g_bin + ((size_t)ch << 18);

  const int c0 = (w << 7) + (lane << 2);
  const int hcol = (lane == 0) ? (c0 - 2) : (c0 + 4);
  const bool hval = (lane == 0) ? (w > 0) : ((lane == 31) && (w < 7));
  const int B0 = Bsh[0];
  unsigned long long accL = 0ull, accH = 0ull;

  auto ldOwn = [&](int y) -> int4 {
    int4 m = make_int4(0, 0, 0, 0);
    if ((unsigned)y < 1024u) {
      float4 v = __ldg(xo + ((size_t)y << 8) + tid);
      m.x = (int)(v.x * 8388608.0f);
      m.y = (int)(v.y * 8388608.0f);
      m.z = (int)(v.z * 8388608.0f);
      m.w = (int)(v.w * 8388608.0f);
    }
    return m;
  };
  auto ldHalo = [&](int y) -> int2 {
    int2 m = make_int2(0, 0);
    if (hval && (unsigned)y < 1024u) {
      float2 v = __ldg((const float2*)(xs + ((size_t)y << 10) + hcol));
      m.x = (int)(v.x * 8388608.0f);
      m.y = (int)(v.y * 8388608.0f);
    }
    return m;
  };
  // smallest k with M > B[k]; 0 if M > B0. Guess +- bounded corrections.
  auto kidx = [&](int M) -> int {
    int d = B0 - M;
    if (d < 0) return 0;
    int k = (int)((float)d * 9.5367432e-06f);
    if (k < 1) k = 1;
    if (k > 1021) k = 1021;
    k += (M <= Bsh[k]);          // up to two upward corrections
    k += (M <= Bsh[k]);
    if (k > 1 && M > Bsh[k - 1]) {   // up to two downward corrections
      k--;
      if (k > 1 && M > Bsh[k - 1]) k--;
    }
    return k;
  };

  int4 r0 = ldOwn(y0 - 2), r1 = ldOwn(y0 - 1), r2 = ldOwn(y0), r3 = ldOwn(y0 + 1);
  int2 h0 = ldHalo(y0 - 2), h1 = ldHalo(y0 - 1), h2 = ldHalo(y0), h3 = ldHalo(y0 + 1);
  int4 S;
  S.x = r0.x + r1.x + r2.x + r3.x;
  S.y = r0.y + r1.y + r2.y + r3.y;
  S.z = r0.z + r1.z + r2.z + r3.z;
  S.w = r0.w + r1.w + r2.w + r3.w;
  int2 Sh = make_int2(h0.x + h1.x + h2.x + h3.x, h0.y + h1.y + h2.y + h3.y);

#pragma unroll 2
  for (int yy = 0; yy < 32; ++yy) {
    const int y = y0 + yy;
    int4 nw = ldOwn(y + 2);
    int2 nh = ldHalo(y + 2);
    S.x += nw.x; S.y += nw.y; S.z += nw.z; S.w += nw.w;
    Sh.x += nh.x; Sh.y += nh.y;

    int l2 = __shfl_up_sync(0xFFFFFFFFu, S.z, 1);
    int l1 = __shfl_up_sync(0xFFFFFFFFu, S.w, 1);
    int q1 = __shfl_down_sync(0xFFFFFFFFu, S.x, 1);
    int q2 = __shfl_down_sync(0xFFFFFFFFu, S.y, 1);
    if (lane == 0)  { l2 = Sh.x; l1 = Sh.y; }
    if (lane == 31) { q1 = Sh.x; q2 = Sh.y; }

    int Mx = l2 + l1 + S.x + S.y + S.z;
    int My = Mx - l2 + S.w;
    int Mz = My - l1 + q1;
    int Mw = Mz - S.x + q2;

    int k0 = kidx(Mx), k1 = kidx(My), k2 = kidx(Mz), k3 = kidx(Mw);
    unsigned p = (unsigned)(k0 > 255 ? 255 : k0)
               | ((unsigned)(k1 > 255 ? 255 : k1) << 8)
               | ((unsigned)(k2 > 255 ? 255 : k2) << 16)
               | ((unsigned)(k3 > 255 ? 255 : k3) << 24);
    bp[((size_t)y << 8) + tid] = p;

    {
      int kc = k0 >> 6; unsigned long long one = 1ull << ((kc & 7) << 3);
      if (kc < 8) accL += one; else accH += one;
      kc = k1 >> 6; one = 1ull << ((kc & 7) << 3);
      if (kc < 8) accL += one; else accH += one;
      kc = k2 >> 6; one = 1ull << ((kc & 7) << 3);
      if (kc < 8) accL += one; else accH += one;
      kc = k3 >> 6; one = 1ull << ((kc & 7) << 3);
      if (kc < 8) accL += one; else accH += one;
    }

    S.x -= r0.x; S.y -= r0.y; S.z -= r0.z; S.w -= r0.w;
    Sh.x -= h0.x; Sh.y -= h0.y;
    r0 = r1; r1 = r2; r2 = r3; r3 = nw;
    h0 = h1; h1 = h2; h2 = h3; h3 = nh;
  }

  // single flush: 32 rows x 4 px = 128 max per 8-bit field
#pragma unroll
  for (int j = 0; j < 8; ++j) {
    int a = (int)((accL >> (j << 3)) & 0xffull);
    int b = (int)((accH >> (j << 3)) & 0xffull);
    if (a) atomicAdd(&csh[j], a);
    if (b) atomicAdd(&csh[8 + j], b);
  }
  __syncthreads();
  if (tid < 16 && csh[tid]) atomicAdd(&g_coarse[tid], csh[tid]);
}

// ---------------------------------------------------------------------------
// K2a: pick the 64-step window containing the 0.84 crossing.
// ---------------------------------------------------------------------------
__global__ void k2a() {
  const float invN = 1.0f / 33554432.0f;   // N = 2^25
  int cum = 0, jstar = -1, cumb = 0;
  for (int j = 0; j < 16; ++j) {
    int nc = cum + g_coarse[j];
    if ((float)nc * invN >= 0.84f) { jstar = j; cumb = cum; cum = nc; break; }
    cum = nc;
  }
  if (jstar < 0) { jstar = 15; cumb = cum - g_coarse[15]; }
  g_lo = jstar << 6;
  g_cumbelow = cumb;
}

// ---------------------------------------------------------------------------
// K2b: fine histogram, atomics only for pixels inside the 64-bin window.
// ---------------------------------------------------------------------------
__global__ void __launch_bounds__(256) k2b() {
  __shared__ int f[64];
  const int tid = threadIdx.x;
  if (tid < 64) f[tid] = 0;
  __syncthreads();
  const unsigned lo = (unsigned)g_lo;
  const uint4* p = (const uint4*)g_bin;
  const int n = NPIX / 16;
  for (int i = blockIdx.x * 256 + tid; i < n; i += gridDim.x * 256) {
    uint4 v = __ldg(p + i);
#pragma unroll
    for (int q = 0; q < 4; ++q) {
      unsigned word = (q == 0) ? v.x : (q == 1) ? v.y : (q == 2) ? v.z : v.w;
#pragma unroll
      for (int b = 0; b < 4; ++b) {
        unsigned t = ((word >> (b << 3)) & 0xffu) - lo;
        if (t < 64u) atomicAdd(&f[t], 1);
      }
    }
  }
  __syncthreads();
  if (tid < 64 && f[tid]) atomicAdd(&g_fine[tid], f[tid]);
}

// ---------------------------------------------------------------------------
// K2c: replay both while-loops exactly on exact counts -> final bin index a.
// ---------------------------------------------------------------------------
__global__ void k2c() {
  const float invN = 1.0f / 33554432.0f;
  int cum = g_cumbelow;
  const int lo = g_lo;
  int i = 0;
  for (; i < 64; ++i) {
    cum += g_fine[i];
    if ((float)cum * invN >= 0.84f) break;
  }
  if (i >= 64) i = 63;
  int a = lo + i;
  if ((float)cum * invN > 0.86f) a -= 1;
  g_a = a;
}

// ---------------------------------------------------------------------------
// K3: threshold (v <= a on uint8 bins) + bitwise morphological close + expand.
// 1024x32 tiles, grid 1024.
// ---------------------------------------------------------------------------
__global__ void __launch_bounds__(256) k_morph(float* __restrict__ out) {
  __shared__ unsigned bits[40][33];
  __shared__ unsigned hd[40][33];
  __shared__ unsigned dv[36][33];
  __shared__ unsigned he[36][33];
  const int tid  = threadIdx.x;
  const int lane = tid & 31;
  const int wid  = tid >> 5;
  const int ch = blockIdx.x >> 5;
  const int y0 = (blockIdx.x & 31) << 5;
  const int a = g_a;
  const unsigned* bw = g_bin + ((size_t)ch << 18);

  for (int r = wid; r < 40; r += 8) {
    const int gy = y0 - 4 + r;
    const bool in = (unsigned)gy < 1024u;
    for (int seg = 0; seg < 8; ++seg) {
      unsigned v = 0;
      if (in) {
        unsigned pk = __ldg(&bw[((size_t)gy << 8) + (seg << 5) + lane]);
        unsigned n = ((int)( pk        & 0xff) <= a ? 1u : 0u)
                   | ((int)((pk >> 8)  & 0xff) <= a ? 2u : 0u)
                   | ((int)((pk >> 16) & 0xff) <= a ? 4u : 0u)
                   | ((int)((pk >> 24) & 0xff) <= a ? 8u : 0u);
        v = n << ((lane & 7) << 2);
        v |= __shfl_xor_sync(0xFFFFFFFFu, v, 1);
        v |= __shfl_xor_sync(0xFFFFFFFFu, v, 2);
        v |= __shfl_xor_sync(0xFFFFFFFFu, v, 4);
      }
      if ((lane & 7) == 0) bits[r][(seg << 2) + (lane >> 3)] = v;
    }
  }
  __syncthreads();

  for (int idx = tid; idx < 40 * 32; idx += 256) {
    const int r = idx >> 5, w = idx & 31;
    const unsigned u = bits[r][w];
    const unsigned L = w ? bits[r][w - 1] : 0u;
    const unsigned R = (w < 31) ? bits[r][w + 1] : 0u;
    hd[r][w] = u | __funnelshift_r(u, R, 1) | __funnelshift_r(u, R, 2)
                 | __funnelshift_l(L, u, 1) | __funnelshift_l(L, u, 2);
  }
  __syncthreads();

  for (int idx = tid; idx < 36 * 32; idx += 256) {
    const int r = idx >> 5, w = idx & 31;
    dv[r][w] = hd[r][w] | hd[r + 1][w] | hd[r + 2][w] | hd[r + 3][w] | hd[r + 4][w];
  }
  __syncthreads();

  for (int idx = tid; idx < 36 * 32; idx += 256) {
    const int r = idx >> 5, w = idx & 31;
    const unsigned u = dv[r][w];
    const unsigned L = w ? dv[r][w - 1] : 0xFFFFFFFFu;
    const unsigned R = (w < 31) ? dv[r][w + 1] : 0xFFFFFFFFu;
    he[r][w] = u & __funnelshift_r(u, R, 1) & __funnelshift_r(u, R, 2)
                 & __funnelshift_l(L, u, 1) & __funnelshift_l(L, u, 2);
  }
  __syncthreads();

  float* op = out + ((size_t)ch << 20);
  for (int idx = tid; idx < 32 * 32; idx += 256) {
    const int yy = idx >> 5, w = idx & 31;
    const int gy = y0 + yy;
    int lo = gy - 2; if (lo < 0) lo = 0;
    int hi = gy + 2; if (hi > 1023) hi = 1023;
    unsigned o = 0xFFFFFFFFu;
    for (int g2 = lo; g2 <= hi; ++g2) o &= he[g2 - (y0 - 2)][w];
    float4* dst = (float4*)(op + ((size_t)gy << 10) + (w << 5));
#pragma unroll
    for (int q = 0; q < 8; ++q) {
      float4 f;
      f.x = ((o >> (4 * q    )) & 1u) ? 1.0f : 0.0f;
      f.y = ((o >> (4 * q + 1)) & 1u) ? 1.0f : 0.0f;
      f.z = ((o >> (4 * q + 2)) & 1u) ? 1.0f : 0.0f;
      f.w = ((o >> (4 * q + 3)) & 1u) ? 1.0f : 0.0f;
      dst[q] = f;
    }
  }
}

// ---------------------------------------------------------------------------
extern "C" void kernel_launch(void* const* d_in, const int* in_sizes, int n_in,
                              void* d_out, int out_size) {
  const float* x = (const float*)d_in[0];
  if (n_in > 1 && in_sizes[0] < in_sizes[1]) x = (const float*)d_in[1];

  k_init <<<1,    256>>>();
  k_blur <<<1024, 256>>>(x);
  k2a    <<<1,    1  >>>();
  k2b    <<<1024, 256>>>();
  k2c    <<<1,    1  >>>();
  k_morph<<<1024, 256>>>((float*)d_out);
}

// round 4
// speedup vs baseline: 1.6861x; 1.3309x over previous
#include <cuda_runtime.h>
#include <cstdint>
#include <math.h>

#define NT    1024
#define NPIX  (8*4*1024*1024)
#define NCELL 8192
#define WLO   80          // fine window covers k in [81, 144]
#define WNB   64

// ---- static device scratch ----
__device__ int g_B[NT];                  // integer boundaries: M > B[k] <=> fp32(M*c) > T[k]
__device__ __align__(16) unsigned char g_lut[NCELL];
__device__ int g_cnt80;                  // count(M > B[80])
__device__ int g_fine[WNB];              // fine histogram: count(u == 81+j)
__device__ int g_hist256[256];           // fallback histogram
__device__ int g_flag, g_a;
__device__ unsigned g_bin[NPIX/4];       // per-pixel exact ladder index (sat 255), 4x u8

__device__ __forceinline__ double wscale() {
  const float W = (float)(1.0 / 25.0);
  return (double)W / 8388608.0;
}

// ---------------------------------------------------------------------------
// K0: fp32 threshold ladder -> exact integer boundaries; zero counters.
// ---------------------------------------------------------------------------
__global__ void k_init() {
  __shared__ float Tsh[NT];
  if (threadIdx.x == 0) {
    float t = 0.5f;
    for (int k = 0; k < NT; ++k) { Tsh[k] = t; t = t - 0.0005f; }
  }
  __syncthreads();
  const double c = wscale();
  for (int k = threadIdx.x; k < NT; k += blockDim.x) {
    float T = Tsh[k];
    double dM = (double)T / c;
    long long Mg = (long long)floor(dM);
    if (Mg < -1) Mg = -1;
    if (Mg > 400000000LL) Mg = 400000000LL;
    while ((float)((double)(Mg + 1) * c) <= T) Mg++;
    while (Mg >= 0 && (float)((double)Mg * c) > T) Mg--;
    g_B[k] = (int)Mg;
  }
  if (threadIdx.x == 0) { g_cnt80 = 0; g_flag = 0; }
  if (threadIdx.x < WNB) g_fine[threadIdx.x] = 0;
  if (threadIdx.x < 256) g_hist256[threadIdx.x] = 0;
}

// ---------------------------------------------------------------------------
// K0b: LUT: cell idx (d = B0 - M, 4096-wide cells) -> exact k at cell top,
//      saturated to 255. Within a cell k grows by at most 1.
// ---------------------------------------------------------------------------
__global__ void k_lut() {
  const int i = blockIdx.x * blockDim.x + threadIdx.x;
  if (i >= NCELL) return;
  const int B0 = g_B[0];
  const int Mh = B0 - (i << 12);      // largest M in cell (smallest d)
  // smallest k in [1,1023] with Mh > B[k] (B monotone decreasing)
  int lo = 1, hi = 1023, res = 1024;
  while (lo <= hi) {
    int mid = (lo + hi) >> 1;
    if (Mh > g_B[mid]) { res = mid; hi = mid - 1; }
    else lo = mid + 1;
  }
  g_lut[i] = (unsigned char)(res > 255 ? 255 : res);
}

// ---------------------------------------------------------------------------
// K1: exact integer 5x5 box blur (running sums) + LUT-exact ladder index,
//     u8 store, register cnt80. 8 warps = 8 x 128-col strips; 32-row band.
// ---------------------------------------------------------------------------
__global__ void __launch_bounds__(256) k_blur(const float* __restrict__ x) {
  __shared__ int Bsh[256];
  __shared__ unsigned char lutsh[NCELL];
  const int tid = threadIdx.x, lane = tid & 31, w = tid >> 5;
  if (tid < 256) Bsh[tid] = g_B[tid];
  {
    const uint4* src = (const uint4*)g_lut;
    uint4* dst = (uint4*)lutsh;
    for (int i = tid; i < NCELL / 16; i += 256) dst[i] = src[i];
  }
  __syncthreads();

  const int ch = blockIdx.x >> 5;
  const int y0 = (blockIdx.x & 31) << 5;
  const float4* xo = (const float4*)x + ((size_t)ch << 18);
  const float*  xs = x + ((size_t)ch << 20);
  unsigned* bp = g_bin + ((size_t)ch << 18);

  const int c0 = (w << 7) + (lane << 2);
  const int hcol = (lane == 0) ? (c0 - 2) : (c0 + 4);
  const bool hval = (lane == 0) ? (w > 0) : ((lane == 31) && (w < 7));
  const int B0 = Bsh[0];
  int cnt80 = 0;

  auto ldOwn = [&](int y) -> int4 {
    int4 m = make_int4(0, 0, 0, 0);
    if ((unsigned)y < 1024u) {
      float4 v = __ldg(xo + ((size_t)y << 8) + tid);
      m.x = (int)(v.x * 8388608.0f);
      m.y = (int)(v.y * 8388608.0f);
      m.z = (int)(v.z * 8388608.0f);
      m.w = (int)(v.w * 8388608.0f);
    }
    return m;
  };
  auto ldHalo = [&](int y) -> int2 {
    int2 m = make_int2(0, 0);
    if (hval && (unsigned)y < 1024u) {
      float2 v = __ldg((const float2*)(xs + ((size_t)y << 10) + hcol));
      m.x = (int)(v.x * 8388608.0f);
      m.y = (int)(v.y * 8388608.0f);
    }
    return m;
  };
  // exact saturated ladder index via LUT (+1 bounded correction)
  auto uidx = [&](int M) -> int {
    const int d = B0 - M;
    int dc = d < 0 ? 0 : d;
    unsigned idx = (unsigned)dc >> 12;
    if (idx > NCELL - 1) idx = NCELL - 1;
    int kb = lutsh[idx];
    int k = kb + (M <= Bsh[kb]);
    if (k > 255) k = 255;
    return d < 0 ? 0 : k;
  };

  int4 r0 = ldOwn(y0 - 2), r1 = ldOwn(y0 - 1), r2 = ldOwn(y0), r3 = ldOwn(y0 + 1);
  int2 h0 = ldHalo(y0 - 2), h1 = ldHalo(y0 - 1), h2 = ldHalo(y0), h3 = ldHalo(y0 + 1);
  int4 S;
  S.x = r0.x + r1.x + r2.x + r3.x;
  S.y = r0.y + r1.y + r2.y + r3.y;
  S.z = r0.z + r1.z + r2.z + r3.z;
  S.w = r0.w + r1.w + r2.w + r3.w;
  int2 Sh = make_int2(h0.x + h1.x + h2.x + h3.x, h0.y + h1.y + h2.y + h3.y);

  for (int yy = 0; yy < 32; ++yy) {
    const int y = y0 + yy;
    int4 nw = ldOwn(y + 2);
    int2 nh = ldHalo(y + 2);
    S.x += nw.x; S.y += nw.y; S.z += nw.z; S.w += nw.w;
    Sh.x += nh.x; Sh.y += nh.y;

    int l2 = __shfl_up_sync(0xFFFFFFFFu, S.z, 1);
    int l1 = __shfl_up_sync(0xFFFFFFFFu, S.w, 1);
    int q1 = __shfl_down_sync(0xFFFFFFFFu, S.x, 1);
    int q2 = __shfl_down_sync(0xFFFFFFFFu, S.y, 1);
    if (lane == 0)  { l2 = Sh.x; l1 = Sh.y; }
    if (lane == 31) { q1 = Sh.x; q2 = Sh.y; }

    int Mx = l2 + l1 + S.x + S.y + S.z;
    int My = Mx - l2 + S.w;
    int Mz = My - l1 + q1;
    int Mw = Mz - S.x + q2;

    const int u0 = uidx(Mx), u1 = uidx(My), u2 = uidx(Mz), u3 = uidx(Mw);
    bp[((size_t)y << 8) + tid] =
        (unsigned)u0 | ((unsigned)u1 << 8) | ((unsigned)u2 << 16) | ((unsigned)u3 << 24);
    cnt80 += (u0 <= WLO) + (u1 <= WLO) + (u2 <= WLO) + (u3 <= WLO);

    S.x -= r0.x; S.y -= r0.y; S.z -= r0.z; S.w -= r0.w;
    Sh.x -= h0.x; Sh.y -= h0.y;
    r0 = r1; r1 = r2; r2 = r3; r3 = nw;
    h0 = h1; h1 = h2; h2 = h3; h3 = nh;
  }

  cnt80 += __shfl_down_sync(0xFFFFFFFFu, cnt80, 16);
  cnt80 += __shfl_down_sync(0xFFFFFFFFu, cnt80, 8);
  cnt80 += __shfl_down_sync(0xFFFFFFFFu, cnt80, 4);
  cnt80 += __shfl_down_sync(0xFFFFFFFFu, cnt80, 2);
  cnt80 += __shfl_down_sync(0xFFFFFFFFu, cnt80, 1);
  if (lane == 0) atomicAdd(&g_cnt80, cnt80);
}

// ---------------------------------------------------------------------------
// K2b: fine histogram over window k in [81, 144].
// ---------------------------------------------------------------------------
__global__ void __launch_bounds__(256) k2b() {
  __shared__ int f[WNB];
  const int tid = threadIdx.x;
  if (tid < WNB) f[tid] = 0;
  __syncthreads();
  const uint4* p = (const uint4*)g_bin;
  const int n = NPIX / 16;
  for (int i = blockIdx.x * 256 + tid; i < n; i += gridDim.x * 256) {
    uint4 v = __ldg(p + i);
#pragma unroll
    for (int q = 0; q < 4; ++q) {
      unsigned word = (q == 0) ? v.x : (q == 1) ? v.y : (q == 2) ? v.z : v.w;
#pragma unroll
      for (int b = 0; b < 4; ++b) {
        unsigned t = ((word >> (b << 3)) & 0xffu) - (WLO + 1);
        if (t < (unsigned)WNB) atomicAdd(&f[t], 1);
      }
    }
  }
  __syncthreads();
  if (tid < WNB && f[tid]) atomicAdd(&g_fine[tid], f[tid]);
}

// ---------------------------------------------------------------------------
// K2c: exact replay of both while-loops on exact counts; verify window.
// ---------------------------------------------------------------------------
__global__ void k2c() {
  const float invN = 1.0f / 33554432.0f;     // N = 2^25
  int flag = 0, a = 0;
  int C = g_cnt80;                           // = count at k = 80
  if ((float)C * invN >= 0.84f) {
    flag = 1;                                // crossing at or before 80
  } else {
    int k = -1;
    for (int j = 0; j < WNB; ++j) {
      C += g_fine[j];
      if ((float)C * invN >= 0.84f) { k = WLO + 1 + j; break; }
    }
    if (k < 0) flag = 1;                     // crossing beyond 144
    else {
      while ((float)C * invN > 0.86f) {      // never fires statistically
        if (k <= WLO) { flag = 1; break; }
        C -= g_fine[k - (WLO + 1)];
        k--;
      }
      a = k;
    }
  }
  g_flag = flag;
  if (!flag) g_a = a;
}

// ---------------------------------------------------------------------------
// K2f/K2g: fallback (never runs): full 256-bin histogram + replay.
// ---------------------------------------------------------------------------
__global__ void __launch_bounds__(256) k2f() {
  if (!g_flag) return;
  __shared__ int h[256];
  const int tid = threadIdx.x;
  h[tid] = 0;
  __syncthreads();
  const uint4* p = (const uint4*)g_bin;
  const int n = NPIX / 16;
  for (int i = blockIdx.x * 256 + tid; i < n; i += gridDim.x * 256) {
    uint4 v = __ldg(p + i);
#pragma unroll
    for (int q = 0; q < 4; ++q) {
      unsigned word = (q == 0) ? v.x : (q == 1) ? v.y : (q == 2) ? v.z : v.w;
      atomicAdd(&h[word & 0xffu], 1);
      atomicAdd(&h[(word >> 8) & 0xffu], 1);
      atomicAdd(&h[(word >> 16) & 0xffu], 1);
      atomicAdd(&h[(word >> 24) & 0xffu], 1);
    }
  }
  __syncthreads();
  if (h[tid]) atomicAdd(&g_hist256[tid], h[tid]);
}
__global__ void k2g() {
  if (!g_flag) return;
  const float invN = 1.0f / 33554432.0f;
  int C = 0, k = 254;
  for (int j = 0; j <= 254; ++j) {
    C += g_hist256[j];
    if ((float)C * invN >= 0.84f) { k = j; break; }
  }
  while (k > 0 && (float)C * invN > 0.86f) { C -= g_hist256[k]; k--; }
  g_a = k;
}

// ---------------------------------------------------------------------------
// K3: threshold (u <= a) + bitwise morphological close + coalesced expand.
// 1024x32 tiles, grid 1024.
// ---------------------------------------------------------------------------
__global__ void __launch_bounds__(256) k_morph(float* __restrict__ out) {
  __shared__ unsigned bits[40][33];
  __shared__ unsigned hd[40][33];
  __shared__ unsigned dv[36][33];
  __shared__ unsigned he[36][33];
  const int tid  = threadIdx.x;
  const int lane = tid & 31;
  const int wid  = tid >> 5;
  const int ch = blockIdx.x >> 5;
  const int y0 = (blockIdx.x & 31) << 5;
  const int a = g_a;
  const unsigned* bw = g_bin + ((size_t)ch << 18);

  for (int r = wid; r < 40; r += 8) {
    const int gy = y0 - 4 + r;
    const bool in = (unsigned)gy < 1024u;
    for (int seg = 0; seg < 8; ++seg) {
      unsigned v = 0;
      if (in) {
        unsigned pk = __ldg(&bw[((size_t)gy << 8) + (seg << 5) + lane]);
        unsigned n = ((int)( pk        & 0xff) <= a ? 1u : 0u)
                   | ((int)((pk >> 8)  & 0xff) <= a ? 2u : 0u)
                   | ((int)((pk >> 16) & 0xff) <= a ? 4u : 0u)
                   | ((int)((pk >> 24) & 0xff) <= a ? 8u : 0u);
        v = n << ((lane & 7) << 2);
        v |= __shfl_xor_sync(0xFFFFFFFFu, v, 1);
        v |= __shfl_xor_sync(0xFFFFFFFFu, v, 2);
        v |= __shfl_xor_sync(0xFFFFFFFFu, v, 4);
      }
      if ((lane & 7) == 0) bits[r][(seg << 2) + (lane >> 3)] = v;
    }
  }
  __syncthreads();

  for (int idx = tid; idx < 40 * 32; idx += 256) {
    const int r = idx >> 5, w = idx & 31;
    const unsigned u = bits[r][w];
    const unsigned L = w ? bits[r][w - 1] : 0u;
    const unsigned R = (w < 31) ? bits[r][w + 1] : 0u;
    hd[r][w] = u | __funnelshift_r(u, R, 1) | __funnelshift_r(u, R, 2)
                 | __funnelshift_l(L, u, 1) | __funnelshift_l(L, u, 2);
  }
  __syncthreads();

  for (int idx = tid; idx < 36 * 32; idx += 256) {
    const int r = idx >> 5, w = idx & 31;
    dv[r][w] = hd[r][w] | hd[r + 1][w] | hd[r + 2][w] | hd[r + 3][w] | hd[r + 4][w];
  }
  __syncthreads();

  for (int idx = tid; idx < 36 * 32; idx += 256) {
    const int r = idx >> 5, w = idx & 31;
    const unsigned u = dv[r][w];
    const unsigned L = w ? dv[r][w - 1] : 0xFFFFFFFFu;
    const unsigned R = (w < 31) ? dv[r][w + 1] : 0xFFFFFFFFu;
    he[r][w] = u & __funnelshift_r(u, R, 1) & __funnelshift_r(u, R, 2)
                 & __funnelshift_l(L, u, 1) & __funnelshift_l(L, u, 2);
  }
  __syncthreads();

  // coalesced expand: warp per (row, 128-px segment); lane l -> float4 at l*4
  float* op = out + ((size_t)ch << 20);
  for (int task = wid; task < 32 * 8; task += 8) {
    const int yy = task >> 3, seg = task & 7;
    const int gy = y0 + yy;
    int lo = gy - 2; if (lo < 0) lo = 0;
    int hi = gy + 2; if (hi > 1023) hi = 1023;
    lo -= (y0 - 2); hi -= (y0 - 2);
    const int word = (seg << 2) + (lane >> 3);
    unsigned o = 0xFFFFFFFFu;
    for (int r = lo; r <= hi; ++r) o &= he[r][word];
    const int sh = (lane & 7) << 2;
    float4 f;
    f.x = ((o >> (sh    )) & 1u) ? 1.0f : 0.0f;
    f.y = ((o >> (sh + 1)) & 1u) ? 1.0f : 0.0f;
    f.z = ((o >> (sh + 2)) & 1u) ? 1.0f : 0.0f;
    f.w = ((o >> (sh + 3)) & 1u) ? 1.0f : 0.0f;
    *(float4*)(op + ((size_t)gy << 10) + (seg << 7) + (lane << 2)) = f;
  }
}

// ---------------------------------------------------------------------------
extern "C" void kernel_launch(void* const* d_in, const int* in_sizes, int n_in,
                              void* d_out, int out_size) {
  const float* x = (const float*)d_in[0];
  if (n_in > 1 && in_sizes[0] < in_sizes[1]) x = (const float*)d_in[1];

  k_init <<<1,    256>>>();
  k_lut  <<<32,   256>>>();
  k_blur <<<1024, 256>>>(x);
  k2b    <<<1024, 256>>>();
  k2c    <<<1,    1  >>>();
  k2f    <<<1024, 256>>>();
  k2g    <<<1,    1  >>>();
  k_morph<<<1024, 256>>>((float*)d_out);
}

// round 5
// speedup vs baseline: 1.9071x; 1.1310x over previous
#include <cuda_runtime.h>
#include <cstdint>
#include <math.h>

#define NT    1024
#define NPIX  (8*4*1024*1024)
#define NCELL 8192
#define WLO   80          // fine window covers k in [81, 144]
#define WNB   64

// ---- static device scratch ----
__device__ int g_B[NT];                  // integer boundaries: M > B[k] <=> fp32(M*c) > T[k]
__device__ __align__(16) unsigned char g_lut[NCELL];
__device__ int g_cnt80;                  // count(M > B[80])
__device__ int g_fine[WNB];              // fine histogram: count(u == 81+j)
__device__ int g_a;
__device__ unsigned g_bin[NPIX/4];       // per-pixel exact ladder index (sat 255), 4x u8

__device__ __forceinline__ double wscale() {
  const float W = (float)(1.0 / 25.0);
  return (double)W / 8388608.0;
}

// ---------------------------------------------------------------------------
// K0: ladder -> exact integer boundaries -> LUT, zero counters. One block.
// ---------------------------------------------------------------------------
__global__ void __launch_bounds__(1024) k_setup() {
  __shared__ float Tsh[NT];
  __shared__ int  Bsh[NT];
  const int t = threadIdx.x;
  if (t == 0) {
    float v = 0.5f;
    for (int k = 0; k < NT; ++k) { Tsh[k] = v; v = v - 0.0005f; }
    g_cnt80 = 0;
  }
  if (t < WNB) g_fine[t] = 0;
  __syncthreads();
  {
    const double c = wscale();
    float T = Tsh[t];
    double dM = (double)T / c;
    long long Mg = (long long)floor(dM);
    if (Mg < -1) Mg = -1;
    if (Mg > 400000000LL) Mg = 400000000LL;
    while ((float)((double)(Mg + 1) * c) <= T) Mg++;
    while (Mg >= 0 && (float)((double)Mg * c) > T) Mg--;
    Bsh[t] = (int)Mg;
    g_B[t] = (int)Mg;
  }
  __syncthreads();
  const int B0 = Bsh[0];
#pragma unroll
  for (int q = 0; q < NCELL / 1024; ++q) {
    const int i = q * 1024 + t;
    const int Mh = B0 - (i << 12);        // largest M in cell
    int lo = 1, hi = 1023, res = 1024;    // smallest k with Mh > B[k]
    while (lo <= hi) {
      int mid = (lo + hi) >> 1;
      if (Mh > Bsh[mid]) { res = mid; hi = mid - 1; }
      else lo = mid + 1;
    }
    g_lut[i] = (unsigned char)(res > 255 ? 255 : res);
  }
}

// ---------------------------------------------------------------------------
// K1: exact integer 5x5 box blur (running sums) + LUT-exact ladder index,
//     u8 store, register cnt80, fused per-warp fine histogram.
//     8 warps = 8 x 128-col strips; 32-row band. Grid 1024.
// ---------------------------------------------------------------------------
__global__ void __launch_bounds__(256) k_blur(const float* __restrict__ x) {
  __shared__ int Bsh[256];
  __shared__ unsigned char lutsh[NCELL];
  __shared__ int fh[8][WNB];             // per-warp privatized fine histogram
  const int tid = threadIdx.x, lane = tid & 31, w = tid >> 5;
  if (tid < 256) Bsh[tid] = g_B[tid];
  {
    const uint4* src = (const uint4*)g_lut;
    uint4* dst = (uint4*)lutsh;
    for (int i = tid; i < NCELL / 16; i += 256) dst[i] = src[i];
  }
  if (lane < WNB) { fh[w][lane] = 0; fh[w][lane + 32] = 0; }
  __syncthreads();

  const int ch = blockIdx.x >> 5;
  const int y0 = (blockIdx.x & 31) << 5;
  const float4* xo = (const float4*)x + ((size_t)ch << 18);
  const float*  xs = x + ((size_t)ch << 20);
  unsigned* bp = g_bin + ((size_t)ch << 18);

  const int c0 = (w << 7) + (lane << 2);
  const int hcol = (lane == 0) ? (c0 - 2) : (c0 + 4);
  const bool hval = (lane == 0) ? (w > 0) : ((lane == 31) && (w < 7));
  const int B0 = Bsh[0];
  int cnt80 = 0;

  auto ldOwn = [&](int y) -> int4 {
    int4 m = make_int4(0, 0, 0, 0);
    if ((unsigned)y < 1024u) {
      float4 v = __ldg(xo + ((size_t)y << 8) + tid);
      m.x = (int)(v.x * 8388608.0f);
      m.y = (int)(v.y * 8388608.0f);
      m.z = (int)(v.z * 8388608.0f);
      m.w = (int)(v.w * 8388608.0f);
    }
    return m;
  };
  auto ldHalo = [&](int y) -> int2 {
    int2 m = make_int2(0, 0);
    if (hval && (unsigned)y < 1024u) {
      float2 v = __ldg((const float2*)(xs + ((size_t)y << 10) + hcol));
      m.x = (int)(v.x * 8388608.0f);
      m.y = (int)(v.y * 8388608.0f);
    }
    return m;
  };
  auto uidx = [&](int M) -> int {
    const int d = B0 - M;
    int dc = d < 0 ? 0 : d;
    unsigned idx = (unsigned)dc >> 12;
    if (idx > NCELL - 1) idx = NCELL - 1;
    int kb = lutsh[idx];
    int k = kb + (M <= Bsh[kb]);
    if (k > 255) k = 255;
    return d < 0 ? 0 : k;
  };
  auto tally = [&](int u) {
    cnt80 += (u <= WLO);
    unsigned tb = (unsigned)(u - (WLO + 1));
    if (tb < (unsigned)WNB) atomicAdd(&fh[w][tb], 1);
  };

  int4 r0 = ldOwn(y0 - 2), r1 = ldOwn(y0 - 1), r2 = ldOwn(y0), r3 = ldOwn(y0 + 1);
  int2 h0 = ldHalo(y0 - 2), h1 = ldHalo(y0 - 1), h2 = ldHalo(y0), h3 = ldHalo(y0 + 1);
  int4 S;
  S.x = r0.x + r1.x + r2.x + r3.x;
  S.y = r0.y + r1.y + r2.y + r3.y;
  S.z = r0.z + r1.z + r2.z + r3.z;
  S.w = r0.w + r1.w + r2.w + r3.w;
  int2 Sh = make_int2(h0.x + h1.x + h2.x + h3.x, h0.y + h1.y + h2.y + h3.y);

  for (int yy = 0; yy < 32; ++yy) {
    const int y = y0 + yy;
    int4 nw = ldOwn(y + 2);
    int2 nh = ldHalo(y + 2);
    S.x += nw.x; S.y += nw.y; S.z += nw.z; S.w += nw.w;
    Sh.x += nh.x; Sh.y += nh.y;

    int l2 = __shfl_up_sync(0xFFFFFFFFu, S.z, 1);
    int l1 = __shfl_up_sync(0xFFFFFFFFu, S.w, 1);
    int q1 = __shfl_down_sync(0xFFFFFFFFu, S.x, 1);
    int q2 = __shfl_down_sync(0xFFFFFFFFu, S.y, 1);
    if (lane == 0)  { l2 = Sh.x; l1 = Sh.y; }
    if (lane == 31) { q1 = Sh.x; q2 = Sh.y; }

    int Mx = l2 + l1 + S.x + S.y + S.z;
    int My = Mx - l2 + S.w;
    int Mz = My - l1 + q1;
    int Mw = Mz - S.x + q2;

    const int u0 = uidx(Mx), u1 = uidx(My), u2 = uidx(Mz), u3 = uidx(Mw);
    bp[((size_t)y << 8) + tid] =
        (unsigned)u0 | ((unsigned)u1 << 8) | ((unsigned)u2 << 16) | ((unsigned)u3 << 24);
    tally(u0); tally(u1); tally(u2); tally(u3);

    S.x -= r0.x; S.y -= r0.y; S.z -= r0.z; S.w -= r0.w;
    Sh.x -= h0.x; Sh.y -= h0.y;
    r0 = r1; r1 = r2; r2 = r3; r3 = nw;
    h0 = h1; h1 = h2; h2 = h3; h3 = nh;
  }

  cnt80 += __shfl_down_sync(0xFFFFFFFFu, cnt80, 16);
  cnt80 += __shfl_down_sync(0xFFFFFFFFu, cnt80, 8);
  cnt80 += __shfl_down_sync(0xFFFFFFFFu, cnt80, 4);
  cnt80 += __shfl_down_sync(0xFFFFFFFFu, cnt80, 2);
  cnt80 += __shfl_down_sync(0xFFFFFFFFu, cnt80, 1);
  if (lane == 0) atomicAdd(&g_cnt80, cnt80);

  __syncthreads();
  if (tid < WNB) {
    int s = fh[0][tid] + fh[1][tid] + fh[2][tid] + fh[3][tid]
          + fh[4][tid] + fh[5][tid] + fh[6][tid] + fh[7][tid];
    if (s) atomicAdd(&g_fine[tid], s);
  }
}

// ---------------------------------------------------------------------------
// K2: exact replay of both while-loops; in-kernel fallback (never taken).
// ---------------------------------------------------------------------------
__global__ void __launch_bounds__(256) k_pick() {
  __shared__ int flag_s;
  __shared__ int h[256];
  const int tid = threadIdx.x;
  if (tid == 0) {
    const float invN = 1.0f / 33554432.0f;   // N = 2^25
    int flag = 0, a = 0;
    int C = g_cnt80;                         // count at k = 80
    if ((float)C * invN >= 0.84f) flag = 1;
    else {
      int k = -1;
      for (int j = 0; j < WNB; ++j) {
        C += g_fine[j];
        if ((float)C * invN >= 0.84f) { k = WLO + 1 + j; break; }
      }
      if (k < 0) flag = 1;
      else {
        while ((float)C * invN > 0.86f) {
          if (k <= WLO) { flag = 1; break; }
          C -= g_fine[k - (WLO + 1)];
          k--;
        }
        a = k;
      }
    }
    flag_s = flag;
    if (!flag) g_a = a;
  }
  __syncthreads();
  if (!flag_s) return;

  // fallback: full 256-bin histogram (single block, slow, statistically never)
  h[tid] = 0;
  __syncthreads();
  const uint4* p = (const uint4*)g_bin;
  const int n = NPIX / 16;
  for (int i = tid; i < n; i += 256) {
    uint4 v = __ldg(p + i);
#pragma unroll
    for (int q = 0; q < 4; ++q) {
      unsigned word = (q == 0) ? v.x : (q == 1) ? v.y : (q == 2) ? v.z : v.w;
      atomicAdd(&h[word & 0xffu], 1);
      atomicAdd(&h[(word >> 8) & 0xffu], 1);
      atomicAdd(&h[(word >> 16) & 0xffu], 1);
      atomicAdd(&h[(word >> 24) & 0xffu], 1);
    }
  }
  __syncthreads();
  if (tid == 0) {
    const float invN = 1.0f / 33554432.0f;
    int C = 0, k = 254;
    for (int j = 0; j <= 254; ++j) {
      C += h[j];
      if ((float)C * invN >= 0.84f) { k = j; break; }
    }
    while (k > 0 && (float)C * invN > 0.86f) { C -= h[k]; k--; }
    g_a = k;
  }
}

// ---------------------------------------------------------------------------
// K3: threshold (u <= a) + bitwise morphological close + coalesced expand.
// 1024x32 tiles, grid 1024.
// ---------------------------------------------------------------------------
__global__ void __launch_bounds__(256) k_morph(float* __restrict__ out) {
  __shared__ unsigned bits[40][33];
  __shared__ unsigned hd[40][33];
  __shared__ unsigned dv[36][33];
  __shared__ unsigned he[36][33];
  const int tid  = threadIdx.x;
  const int lane = tid & 31;
  const int wid  = tid >> 5;
  const int ch = blockIdx.x >> 5;
  const int y0 = (blockIdx.x & 31) << 5;
  const int a = g_a;
  const unsigned* bw = g_bin + ((size_t)ch << 18);

  for (int r = wid; r < 40; r += 8) {
    const int gy = y0 - 4 + r;
    const bool in = (unsigned)gy < 1024u;
    for (int seg = 0; seg < 8; ++seg) {
      unsigned v = 0;
      if (in) {
        unsigned pk = __ldg(&bw[((size_t)gy << 8) + (seg << 5) + lane]);
        unsigned n = ((int)( pk        & 0xff) <= a ? 1u : 0u)
                   | ((int)((pk >> 8)  & 0xff) <= a ? 2u : 0u)
                   | ((int)((pk >> 16) & 0xff) <= a ? 4u : 0u)
                   | ((int)((pk >> 24) & 0xff) <= a ? 8u : 0u);
        v = n << ((lane & 7) << 2);
        v |= __shfl_xor_sync(0xFFFFFFFFu, v, 1);
        v |= __shfl_xor_sync(0xFFFFFFFFu, v, 2);
        v |= __shfl_xor_sync(0xFFFFFFFFu, v, 4);
      }
      if ((lane & 7) == 0) bits[r][(seg << 2) + (lane >> 3)] = v;
    }
  }
  __syncthreads();

  for (int idx = tid; idx < 40 * 32; idx += 256) {
    const int r = idx >> 5, w = idx & 31;
    const unsigned u = bits[r][w];
    const unsigned L = w ? bits[r][w - 1] : 0u;
    const unsigned R = (w < 31) ? bits[r][w + 1] : 0u;
    hd[r][w] = u | __funnelshift_r(u, R, 1) | __funnelshift_r(u, R, 2)
                 | __funnelshift_l(L, u, 1) | __funnelshift_l(L, u, 2);
  }
  __syncthreads();

  for (int idx = tid; idx < 36 * 32; idx += 256) {
    const int r = idx >> 5, w = idx & 31;
    dv[r][w] = hd[r][w] | hd[r + 1][w] | hd[r + 2][w] | hd[r + 3][w] | hd[r + 4][w];
  }
  __syncthreads();

  for (int idx = tid; idx < 36 * 32; idx += 256) {
    const int r = idx >> 5, w = idx & 31;
    const unsigned u = dv[r][w];
    const unsigned L = w ? dv[r][w - 1] : 0xFFFFFFFFu;
    const unsigned R = (w < 31) ? dv[r][w + 1] : 0xFFFFFFFFu;
    he[r][w] = u & __funnelshift_r(u, R, 1) & __funnelshift_r(u, R, 2)
                 & __funnelshift_l(L, u, 1) & __funnelshift_l(L, u, 2);
  }
  __syncthreads();

  float* op = out + ((size_t)ch << 20);
  for (int task = wid; task < 32 * 8; task += 8) {
    const int yy = task >> 3, seg = task & 7;
    const int gy = y0 + yy;
    int lo = gy - 2; if (lo < 0) lo = 0;
    int hi = gy + 2; if (hi > 1023) hi = 1023;
    lo -= (y0 - 2); hi -= (y0 - 2);
    const int word = (seg << 2) + (lane >> 3);
    unsigned o = 0xFFFFFFFFu;
    for (int r = lo; r <= hi; ++r) o &= he[r][word];
    const int sh = (lane & 7) << 2;
    float4 f;
    f.x = ((o >> (sh    )) & 1u) ? 1.0f : 0.0f;
    f.y = ((o >> (sh + 1)) & 1u) ? 1.0f : 0.0f;
    f.z = ((o >> (sh + 2)) & 1u) ? 1.0f : 0.0f;
    f.w = ((o >> (sh + 3)) & 1u) ? 1.0f : 0.0f;
    *(float4*)(op + ((size_t)gy << 10) + (seg << 7) + (lane << 2)) = f;
  }
}

// ---------------------------------------------------------------------------
extern "C" void kernel_launch(void* const* d_in, const int* in_sizes, int n_in,
                              void* d_out, int out_size) {
  const float* x = (const float*)d_in[0];
  if (n_in > 1 && in_sizes[0] < in_sizes[1]) x = (const float*)d_in[1];

  k_setup<<<1,    1024>>>();
  k_blur <<<1024, 256 >>>(x);
  k_pick <<<1,    256 >>>();
  k_morph<<<1024, 256 >>>((float*)d_out);
}